// round 7
// baseline (speedup 1.0000x reference)
#include <cuda_runtime.h>
#include <cuda_bf16.h>
#include <math.h>

// Problem constants
#define B      256
#define NNEG   1000
#define H      3
#define D      128
#define CMAX   250          // neg indices < min(NUM_CLUSTER) = 250
#define CP     256          // padded cluster dim (252..255 zero)
#define EPSF   1e-6f
#define BPB    4            // b's per block
#define NBLK   (B / BPB)    // 64 blocks

// Dynamic smem layout (bytes)
#define OFF_CN    0                         // float cn[D][CP]      = 131072
#define OFF_PN    (D * CP * 4)              // float pnorm[4][CP]   = 4096
#define OFF_PART  (OFF_PN + 4 * CP * 4)     // float part[4][64][4][4] = 16384
#define DSMEM_SZ  (OFF_PART + BPB * 64 * 4 * 4 * 4)   // 151552 B

// Device globals (no allocation allowed)
__device__ float g_loss[B];
__device__ unsigned int g_done = 0;

__global__ void __launch_bounds__(1024, 1)
hirl_all(const float* __restrict__ se,
         const float* __restrict__ c0,
         const float* __restrict__ c1,
         const float* __restrict__ c2,
         const int* __restrict__ i2c0,
         const int* __restrict__ i2c1,
         const int* __restrict__ i2c2,
         const int* __restrict__ index,
         const int* __restrict__ neg,
         float* __restrict__ out) {
    extern __shared__ float dsm[];
    float* cn    = dsm;                          // [d][c] raw centroid tile
    float* pnorm = dsm + OFF_PN / 4;             // [ds][c] norm partials
    float* part  = dsm + OFF_PART / 4;           // [bl][cg][ds][4] dot partials

    __shared__ float4 se_s[12 * 32];             // 12 se rows [row][d/4] (6 KB)
    __shared__ float  sInvSe[12];
    __shared__ float  S_s[BPB * H * CP];         // local sim matrix (12 KB)
    __shared__ float  posmul_s[BPB];
    __shared__ int    lab_s[BPB][H];
    __shared__ float  rQ[BPB][8];
    __shared__ float  cQ[BPB][8];
    __shared__ int    sLast;

    const int tid  = threadIdx.x;
    const int w    = tid >> 5;
    const int lane = tid & 31;
    const int b0   = blockIdx.x * BPB;
    const float* se_f = (const float*)se_s;

    // ---- Phase -1: this block's neg triples into registers (hides DRAM) ----
    const int q = tid >> 8, local = tid & 255;        // quarter q owns b0+q
    const bool active = (local < 250);                // 250 thr x 4 negs = 1000
    int4 na, nb, nc;
    if (active) {
        const int4* p = (const int4*)(neg + ((size_t)(b0 + q) * NNEG + local * 4) * H);
        na = p[0]; nb = p[1]; nc = p[2];
    }

    // ---- Phase 0: se rows + norms (warps 0-11), pos path (warps 12-15) ----
    if (w < 12) {
        int bl = w / 3, h = w - bl * 3;
        float4 v = ((const float4*)(se + ((size_t)(b0 + bl) * H + h) * D))[lane];
        se_s[w * 32 + lane] = v;
        float s = v.x * v.x + v.y * v.y + v.z * v.z + v.w * v.w;
        #pragma unroll
        for (int o = 16; o > 0; o >>= 1) s += __shfl_xor_sync(0xffffffffu, s, o);
        if (lane == 0) sInvSe[w] = 1.0f / fmaxf(sqrtf(s), 1e-12f);
    } else if (w < 16) {
        int b = b0 + (w - 12);
        int idx = index[b];
        int lab0 = i2c0[idx], lab1 = i2c1[idx], lab2 = i2c2[idx];
        float4 cv0 = ((const float4*)(c0 + (size_t)lab0 * D))[lane];
        float4 cv1 = ((const float4*)(c1 + (size_t)lab1 * D))[lane];
        float4 cv2 = ((const float4*)(c2 + (size_t)lab2 * D))[lane];
        float4 sv0 = ((const float4*)(se + ((size_t)b * H + 0) * D))[lane];
        float4 sv1 = ((const float4*)(se + ((size_t)b * H + 1) * D))[lane];
        float4 sv2 = ((const float4*)(se + ((size_t)b * H + 2) * D))[lane];
        float prod = 1.0f;
        #pragma unroll
        for (int h = 0; h < H; h++) {
            float4 cv = (h == 0) ? cv0 : (h == 1) ? cv1 : cv2;
            float4 sv = (h == 0) ? sv0 : (h == 1) ? sv1 : sv2;
            float cc = cv.x * cv.x + cv.y * cv.y + cv.z * cv.z + cv.w * cv.w;
            float ee = sv.x * sv.x + sv.y * sv.y + sv.z * sv.z + sv.w * sv.w;
            float dd = cv.x * sv.x + cv.y * sv.y + cv.z * sv.z + cv.w * sv.w;
            #pragma unroll
            for (int o = 16; o > 0; o >>= 1) {
                cc += __shfl_xor_sync(0xffffffffu, cc, o);
                ee += __shfl_xor_sync(0xffffffffu, ee, o);
                dd += __shfl_xor_sync(0xffffffffu, dd, o);
            }
            float s = dd / (fmaxf(sqrtf(cc), 1e-12f) * fmaxf(sqrtf(ee), 1e-12f));
            prod *= (s + 1.0f) * 0.5f;
        }
        if (lane == 0) {
            posmul_s[w - 12] = prod;
            lab_s[w - 12][0] = lab0;
            lab_s[w - 12][1] = lab1;
            lab_s[w - 12][2] = lab2;
        }
    }

    // ---- Phase 1: 3 tiles (one per hierarchy), each = 256 padded c's ----
    for (int h = 0; h < H; h++) {
        const float* cents = (h == 0) ? c0 : (h == 1) ? c1 : c2;

        // Load tile transposed: cn[d][c]. 8192 float4 chunks, 8 per thread.
        #pragma unroll
        for (int k = 0; k < 8; k++) {
            int i = tid + k * 1024;
            int c = i & 255, dq = i >> 8;       // dq = float4 index 0..31
            float4 v = make_float4(0.f, 0.f, 0.f, 0.f);
            if (c < CMAX) v = ((const float4*)(cents + (size_t)c * D))[dq];
            int d = dq * 4;
            cn[(d + 0) * CP + c] = v.x;
            cn[(d + 1) * CP + c] = v.y;
            cn[(d + 2) * CP + c] = v.z;
            cn[(d + 3) * CP + c] = v.w;
        }
        __syncthreads();

        // Dot pass: thread = (bl = tid>>8, ds = (tid>>6)&3, cg = tid&63).
        {
            int cg = tid & 63, ds = (tid >> 6) & 3, bl = tid >> 8;
            const float* cnp = cn + (ds * 32) * CP + cg * 4;
            const float* ses = se_f + (bl * 3 + h) * D + ds * 32;
            float a0 = 0.f, a1 = 0.f, a2 = 0.f, a3 = 0.f;
            #pragma unroll 8
            for (int d = 0; d < 32; d++) {
                float4 cv = *((const float4*)(cnp + d * CP));
                float sv = ses[d];
                a0 = fmaf(sv, cv.x, a0);
                a1 = fmaf(sv, cv.y, a1);
                a2 = fmaf(sv, cv.z, a2);
                a3 = fmaf(sv, cv.w, a3);
            }
            *((float4*)(part + (((bl * 64 + cg) * 4 + ds) * 4))) =
                make_float4(a0, a1, a2, a3);
        }
        // Norm pass (reuses smem tile): thread = (ds2 = tid>>8, c = tid&255).
        {
            int c = tid & 255, ds2 = tid >> 8;
            const float* cnp = cn + (ds2 * 32) * CP + c;
            float ss = 0.0f;
            #pragma unroll 8
            for (int d = 0; d < 32; d++) {
                float x = cnp[d * CP];
                ss = fmaf(x, x, ss);
            }
            pnorm[ds2 * CP + c] = ss;
        }
        __syncthreads();

        // Combine: thread = (bl = tid>>8, c = tid&255).
        {
            int c = tid & 255, bl = tid >> 8;
            float ss = pnorm[c] + pnorm[CP + c] + pnorm[2 * CP + c] + pnorm[3 * CP + c];
            float invc = 1.0f / fmaxf(sqrtf(ss), 1e-12f);
            const float* pp = part + ((bl * 64 + (c >> 2)) * 4) * 4 + (c & 3);
            float dot = pp[0] + pp[4] + pp[8] + pp[12];
            S_s[(bl * 3 + h) * CP + c] =
                (dot * invc * sInvSe[bl * 3 + h] + 1.0f) * 0.5f;
        }
        __syncthreads();
    }

    // ---- Phase 2: loss from register-held neg indices + smem S ----
    float sumL = 0.0f, cnt = 0.0f;
    if (active) {
        const int lab0 = lab_s[q][0], lab1 = lab_s[q][1], lab2 = lab_s[q][2];
        const float* Sq = S_s + q * (H * CP);
        int idx0[4] = { na.x, na.w, nb.z, nc.y };
        int idx1[4] = { na.y, nb.x, nb.w, nc.z };
        int idx2[4] = { na.z, nb.y, nc.x, nc.w };
        #pragma unroll
        for (int k = 0; k < 4; k++) {
            int i0 = idx0[k], i1 = idx1[k], i2 = idx2[k];
            float prod = Sq[i0] * Sq[CP + i1] * Sq[2 * CP + i2];
            bool tn = (i0 != lab0) || (i1 != lab1) || (i2 != lab2);
            if (tn) {
                sumL += -__logf(1.0f - prod + EPSF);
                cnt  += 1.0f;
            }
        }
    }
    #pragma unroll
    for (int o = 16; o > 0; o >>= 1) {
        sumL += __shfl_xor_sync(0xffffffffu, sumL, o);
        cnt  += __shfl_xor_sync(0xffffffffu, cnt,  o);
    }
    if (lane == 0) { rQ[q][w & 7] = sumL; cQ[q][w & 7] = cnt; }
    __syncthreads();

    if ((tid & 255) == 0) {          // 4 threads, one per quarter
        float sL = 0.0f, sC = 0.0f;
        #pragma unroll
        for (int i = 0; i < 8; i++) { sL += rQ[q][i]; sC += cQ[q][i]; }
        float negl = sL / (sC + EPSF);
        float posl = -__logf(posmul_s[q] + EPSF);
        g_loss[b0 + q] = 0.5f * (posl + negl);
        __threadfence();
    }
    __syncthreads();

    if (tid == 0) {
        unsigned int t = atomicAdd(&g_done, 1u);
        sLast = (t == (unsigned)(NBLK - 1)) ? 1 : 0;
    }
    __syncthreads();

    // ---- Last block: deterministic final mean over B=256 losses ----
    if (sLast) {
        __threadfence();
        float v = 0.0f;
        if (tid < B) v = *((volatile float*)&g_loss[tid]);
        if (tid < 256) {
            #pragma unroll
            for (int o = 16; o > 0; o >>= 1) v += __shfl_xor_sync(0xffffffffu, v, o);
            if (lane == 0) rQ[0][w] = v;   // w in 0..7
        }
        __syncthreads();
        if (tid == 0) {
            float total = 0.0f;
            #pragma unroll
            for (int i = 0; i < 8; i++) total += rQ[0][i];
            out[0] = total * (1.0f / (float)B);
            g_done = 0;   // reset for next graph replay
        }
    }
}

// ---------------------------------------------------------------------------
extern "C" void kernel_launch(void* const* d_in, const int* in_sizes, int n_in,
                              void* d_out, int out_size) {
    const float* se  = (const float*)d_in[0];
    const float* c0  = (const float*)d_in[1];
    const float* c1  = (const float*)d_in[2];
    const float* c2  = (const float*)d_in[3];
    const int* i2c0  = (const int*)d_in[4];
    const int* i2c1  = (const int*)d_in[5];
    const int* i2c2  = (const int*)d_in[6];
    const int* index = (const int*)d_in[7];
    const int* neg   = (const int*)d_in[8];
    float* out = (float*)d_out;

    cudaFuncSetAttribute(hirl_all, cudaFuncAttributeMaxDynamicSharedMemorySize,
                         DSMEM_SZ);
    hirl_all<<<NBLK, 1024, DSMEM_SZ>>>(se, c0, c1, c2, i2c0, i2c1, i2c2,
                                       index, neg, out);
}

// round 8
// speedup vs baseline: 1.6593x; 1.6593x over previous
#include <cuda_runtime.h>
#include <cuda_bf16.h>
#include <math.h>

// Problem constants
#define B      256
#define NNEG   1000
#define H      3
#define D      128
#define CMAX   250          // neg indices < min(NUM_CLUSTER) = 250
#define CPAD   256          // padded cluster dim
#define EPSF   1e-6f
#define CT     64           // c-tile width
#define BT     16           // b-tile height

// Device globals (no allocation allowed)
__device__ float g_S[B * H * CPAD];       // sim matrix (dot+1)/2, [b][h][c]
__device__ float g_posmul[B];             // prod over h of (pos_sim+1)/2
__device__ int   g_lab[B * H];            // positive labels
__device__ float g_loss[B];               // per-sample loss
__device__ unsigned int g_done = 0;       // completion counter

// ---------------------------------------------------------------------------
// K1: fused normalize + sim (register-tiled) + pos-path precompute.
//     grid = (4, 16, 4), block = 256.
//       z<3          : sim tile (c-tile x, b-tile y, hierarchy z)
//       z==3         : block id = y*4+x (0..63), warps 0-3: pos path.
//     Triggers dependent launch (PDL) once this CTA's stores are done.
// ---------------------------------------------------------------------------
__global__ void k_sim(const float* __restrict__ se,
                      const float* __restrict__ c0,
                      const float* __restrict__ c1,
                      const float* __restrict__ c2,
                      const int* __restrict__ i2c0,
                      const int* __restrict__ i2c1,
                      const int* __restrict__ i2c2,
                      const int* __restrict__ index) {
    __shared__ float cn_s[D * CT];      // raw centroid tile, [d][c] (32 KB)
    __shared__ float se_s[BT * D];      // raw se tile, [bi][d]      (8 KB)
    __shared__ float sPart[4 * CT];     // centroid norm partials [seg][c]
    __shared__ float sInvC[CT];
    __shared__ float sInvSe[BT];

    const int tid = threadIdx.x;

    if (blockIdx.z == 3) {
        int id = blockIdx.y * 4 + blockIdx.x;   // 0..63
        int w = tid >> 5, lane = tid & 31;
        if (w < 4) {
            int b = id * 4 + w;
            int idx = index[b];
            int lab0 = i2c0[idx], lab1 = i2c1[idx], lab2 = i2c2[idx];
            float4 cv0 = ((const float4*)(c0 + (size_t)lab0 * D))[lane];
            float4 cv1 = ((const float4*)(c1 + (size_t)lab1 * D))[lane];
            float4 cv2 = ((const float4*)(c2 + (size_t)lab2 * D))[lane];
            float4 sv0 = ((const float4*)(se + ((size_t)b * H + 0) * D))[lane];
            float4 sv1 = ((const float4*)(se + ((size_t)b * H + 1) * D))[lane];
            float4 sv2 = ((const float4*)(se + ((size_t)b * H + 2) * D))[lane];

            float prod = 1.0f;
            #pragma unroll
            for (int h = 0; h < H; h++) {
                float4 cv = (h == 0) ? cv0 : (h == 1) ? cv1 : cv2;
                float4 sv = (h == 0) ? sv0 : (h == 1) ? sv1 : sv2;
                float cc = cv.x * cv.x + cv.y * cv.y + cv.z * cv.z + cv.w * cv.w;
                float ee = sv.x * sv.x + sv.y * sv.y + sv.z * sv.z + sv.w * sv.w;
                float dd = cv.x * sv.x + cv.y * sv.y + cv.z * sv.z + cv.w * sv.w;
                #pragma unroll
                for (int o = 16; o > 0; o >>= 1) {
                    cc += __shfl_xor_sync(0xffffffffu, cc, o);
                    ee += __shfl_xor_sync(0xffffffffu, ee, o);
                    dd += __shfl_xor_sync(0xffffffffu, dd, o);
                }
                float s = dd / (fmaxf(sqrtf(cc), 1e-12f) * fmaxf(sqrtf(ee), 1e-12f));
                prod *= (s + 1.0f) * 0.5f;
            }
            if (lane == 0) {
                g_posmul[b] = prod;
                g_lab[b * H + 0] = lab0;
                g_lab[b * H + 1] = lab1;
                g_lab[b * H + 2] = lab2;
            }
        }
        __syncthreads();   // order stores before the PDL trigger
        asm volatile("griddepcontrol.launch_dependents;" ::: "memory");
        return;
    }

    // ---- sim tile: BT=16 b's x CT=64 c's, 4 outputs per thread ----
    const int h = blockIdx.z;
    const int cbase = blockIdx.x * CT;
    const int b0 = blockIdx.y * BT;
    const float* cents = (h == 0) ? c0 : (h == 1) ? c1 : c2;

    // Load 64 centroid rows (raw), transposed into cn_s[d][c].
    for (int i = tid; i < CT * 32; i += 256) {     // 2048 float4 chunks
        int c = i & (CT - 1), dq = i >> 6;
        int cg = cbase + c;
        float4 v = make_float4(0.f, 0.f, 0.f, 0.f);
        if (cg < CMAX) v = ((const float4*)(cents + (size_t)cg * D))[dq];
        int d = dq * 4;
        cn_s[(d + 0) * CT + c] = v.x;
        cn_s[(d + 1) * CT + c] = v.y;
        cn_s[(d + 2) * CT + c] = v.z;
        cn_s[(d + 3) * CT + c] = v.w;
    }
    // Load 16 se rows (raw) [bi][d].
    for (int i = tid; i < BT * 32; i += 256) {     // 512 float4 chunks
        int bb = i >> 5, dq = i & 31;
        float4 v = ((const float4*)(se + ((size_t)(b0 + bb) * H + h) * D))[dq];
        int d = dq * 4;
        se_s[bb * D + d + 0] = v.x;
        se_s[bb * D + d + 1] = v.y;
        se_s[bb * D + d + 2] = v.z;
        se_s[bb * D + d + 3] = v.w;
    }
    __syncthreads();

    // Centroid norm partials: seg = tid>>6 (0..3) sums 32 d's for c = tid&63.
    {
        int c = tid & (CT - 1), seg = tid >> 6;
        float ss = 0.0f;
        #pragma unroll
        for (int d = seg * 32; d < seg * 32 + 32; d++) {
            float x = cn_s[d * CT + c];
            ss = fmaf(x, x, ss);
        }
        sPart[seg * CT + c] = ss;
    }
    // se norms: warp w handles rows 2w, 2w+1.
    {
        int w = tid >> 5, lane = tid & 31;
        #pragma unroll
        for (int r = 0; r < 2; r++) {
            int row = w * 2 + r;
            float4 v = ((const float4*)(se_s + row * D))[lane];
            float s = v.x * v.x + v.y * v.y + v.z * v.z + v.w * v.w;
            #pragma unroll
            for (int o = 16; o > 0; o >>= 1) s += __shfl_xor_sync(0xffffffffu, s, o);
            if (lane == 0) sInvSe[row] = 1.0f / fmaxf(sqrtf(s), 1e-12f);
        }
    }
    __syncthreads();
    if (tid < CT) {
        float ss = sPart[tid] + sPart[CT + tid] + sPart[2 * CT + tid] + sPart[3 * CT + tid];
        sInvC[tid] = 1.0f / fmaxf(sqrtf(ss), 1e-12f);
    }
    __syncthreads();

    // Main loop: thread (bi = tid>>4, ci = tid&15) computes c = ci*4 .. +3.
    {
        int bi = tid >> 4, ci = tid & 15;
        int cq = ci * 4;
        float a0 = 0.f, a1 = 0.f, a2 = 0.f, a3 = 0.f;
        const float* ses = se_s + bi * D;
        #pragma unroll 8
        for (int d = 0; d < D; d++) {
            float sv = ses[d];
            float4 cv = *((const float4*)(cn_s + d * CT + cq));
            a0 = fmaf(sv, cv.x, a0);
            a1 = fmaf(sv, cv.y, a1);
            a2 = fmaf(sv, cv.z, a2);
            a3 = fmaf(sv, cv.w, a3);
        }
        float invse = sInvSe[bi];
        float4 r;
        r.x = (a0 * sInvC[cq + 0] * invse + 1.0f) * 0.5f;
        r.y = (a1 * sInvC[cq + 1] * invse + 1.0f) * 0.5f;
        r.z = (a2 * sInvC[cq + 2] * invse + 1.0f) * 0.5f;
        r.w = (a3 * sInvC[cq + 3] * invse + 1.0f) * 0.5f;
        *((float4*)(g_S + ((size_t)(b0 + bi) * H + h) * CPAD + cbase + cq)) = r;
    }
    __syncthreads();   // order g_S stores before the PDL trigger
    asm volatile("griddepcontrol.launch_dependents;" ::: "memory");
}

// ---------------------------------------------------------------------------
// K2 (PDL secondary): prelude loads neg triples into registers BEFORE the
//     griddepcontrol.wait (overlaps with k_sim). Post-wait: labels + g_S
//     lookups + log + reduction. Last block does the final mean.
// ---------------------------------------------------------------------------
__global__ void __launch_bounds__(1024)
k_loss(const int* __restrict__ neg, float* __restrict__ out) {
    __shared__ float rL[32];
    __shared__ int   rC[32];
    __shared__ int   sLast;

    const int b = blockIdx.x, tid = threadIdx.x;
    const int w = tid >> 5, lane = tid & 31;

    // ---- prelude (runs while k_sim is still executing) ----
    int i0 = 0, i1 = 0, i2 = 0;
    const bool on = (tid < NNEG);
    if (on) {
        const int* p = neg + ((size_t)b * NNEG + tid) * H;
        i0 = p[0]; i1 = p[1]; i2 = p[2];
    }

    // ---- wait for k_sim's results to be visible ----
    asm volatile("griddepcontrol.wait;" ::: "memory");

    const int lab0 = g_lab[b * H + 0];
    const int lab1 = g_lab[b * H + 1];
    const int lab2 = g_lab[b * H + 2];

    float sumL = 0.0f;
    bool tn = false;
    if (on) {
        float s0 = __ldg(&g_S[((size_t)b * H + 0) * CPAD + i0]);
        float s1 = __ldg(&g_S[((size_t)b * H + 1) * CPAD + i1]);
        float s2 = __ldg(&g_S[((size_t)b * H + 2) * CPAD + i2]);
        float prod = s0 * s1 * s2;
        tn = (i0 != lab0) || (i1 != lab1) || (i2 != lab2);
        if (tn) sumL = -__logf(1.0f - prod + EPSF);
    }
    unsigned bm = __ballot_sync(0xffffffffu, tn);
    #pragma unroll
    for (int o = 16; o > 0; o >>= 1)
        sumL += __shfl_xor_sync(0xffffffffu, sumL, o);
    if (lane == 0) { rL[w] = sumL; rC[w] = __popc(bm); }
    __syncthreads();
    if (tid < 32) {
        float sL = rL[tid];
        float sC = (float)rC[tid];
        #pragma unroll
        for (int o = 16; o > 0; o >>= 1) {
            sL += __shfl_xor_sync(0xffffffffu, sL, o);
            sC += __shfl_xor_sync(0xffffffffu, sC, o);
        }
        if (tid == 0) {
            float negl = sL / (sC + EPSF);
            float posl = -__logf(g_posmul[b] + EPSF);
            g_loss[b] = 0.5f * (posl + negl);
            __threadfence();
            unsigned int t = atomicAdd(&g_done, 1u);
            sLast = (t == gridDim.x - 1) ? 1 : 0;
        }
    }
    __syncthreads();

    if (sLast) {
        __threadfence();
        float v = 0.0f;
        if (tid < B) v = *((volatile float*)&g_loss[tid]);
        if (tid < 256) {
            #pragma unroll
            for (int o = 16; o > 0; o >>= 1) v += __shfl_xor_sync(0xffffffffu, v, o);
            if (lane == 0) rL[w] = v;   // w in 0..7
        }
        __syncthreads();
        if (tid == 0) {
            float total = 0.0f;
            #pragma unroll
            for (int i = 0; i < 8; i++) total += rL[i];
            out[0] = total * (1.0f / (float)B);
            g_done = 0;   // reset for next graph replay
        }
    }
}

// ---------------------------------------------------------------------------
extern "C" void kernel_launch(void* const* d_in, const int* in_sizes, int n_in,
                              void* d_out, int out_size) {
    const float* se  = (const float*)d_in[0];
    const float* c0  = (const float*)d_in[1];
    const float* c1  = (const float*)d_in[2];
    const float* c2  = (const float*)d_in[3];
    const int* i2c0  = (const int*)d_in[4];
    const int* i2c1  = (const int*)d_in[5];
    const int* i2c2  = (const int*)d_in[6];
    const int* index = (const int*)d_in[7];
    const int* neg   = (const int*)d_in[8];
    float* out = (float*)d_out;

    k_sim<<<dim3(4, 16, 4), 256>>>(se, c0, c1, c2, i2c0, i2c1, i2c2, index);

    // k_loss as PDL secondary: its prelude overlaps with k_sim execution.
    cudaLaunchConfig_t cfg = {};
    cfg.gridDim  = dim3(B, 1, 1);
    cfg.blockDim = dim3(1024, 1, 1);
    cfg.dynamicSmemBytes = 0;
    cudaLaunchAttribute attrs[1];
    attrs[0].id = cudaLaunchAttributeProgrammaticStreamSerialization;
    attrs[0].val.programmaticStreamSerializationAllowed = 1;
    cfg.attrs = attrs;
    cfg.numAttrs = 1;
    cudaLaunchKernelEx(&cfg, k_loss, neg, (float*)d_out);
}

// round 9
// speedup vs baseline: 1.7686x; 1.0659x over previous
#include <cuda_runtime.h>
#include <cuda_bf16.h>
#include <math.h>

// Problem constants
#define B      256
#define NNEG   1000
#define H      3
#define D      128
#define CMAX   250          // neg indices < min(NUM_CLUSTER) = 250
#define CPAD   256          // padded cluster dim
#define EPSF   1e-6f
#define CT     64           // c-tile width
#define BT     16           // b-tile height

// Device globals (no allocation allowed)
__device__ float g_S[B * H * CPAD];       // sim matrix (dot+1)/2, [b][h][c]
__device__ float g_posmul[B];             // prod over h of (pos_sim+1)/2
__device__ int   g_lab[B * H];            // positive labels
__device__ float g_loss[B];               // per-sample loss
__device__ unsigned int g_done = 0;       // completion counter

// ---------------------------------------------------------------------------
// K1: fused normalize + sim (register-tiled) + pos-path precompute.
//     grid = (4, 16, 4), block = 256.
//       z<3  : sim tile (c-tile x, b-tile y, hierarchy z)
//       z==3 : block id = y*4+x (0..63), warps 0-3: pos path for b = id*4+w.
// ---------------------------------------------------------------------------
__global__ void k_sim(const float* __restrict__ se,
                      const float* __restrict__ c0,
                      const float* __restrict__ c1,
                      const float* __restrict__ c2,
                      const int* __restrict__ i2c0,
                      const int* __restrict__ i2c1,
                      const int* __restrict__ i2c2,
                      const int* __restrict__ index) {
    __shared__ float cn_s[D * CT];      // raw centroid tile, [d][c] (32 KB)
    __shared__ float se_s[BT * D];      // raw se tile, [bi][d]      (8 KB)
    __shared__ float sPart[4 * CT];     // centroid norm partials [seg][c]
    __shared__ float sInvC[CT];
    __shared__ float sInvSe[BT];

    const int tid = threadIdx.x;

    if (blockIdx.z == 3) {
        if (blockIdx.x != 0) return;
        int id = blockIdx.y;                 // 0..15, but we need 64 ids
        int w = tid >> 5, lane = tid & 31;
        // 8 warps -> 8 b's per block would give 128; use 4 b's per warp-quad:
        // each of 16 blocks covers 16 b's: warp w handles b = id*16 + w*2 + r
        #pragma unroll
        for (int r = 0; r < 2; r++) {
            int b = id * 16 + w * 2 + r;
            int idx = index[b];
            int lab0 = i2c0[idx], lab1 = i2c1[idx], lab2 = i2c2[idx];
            float4 cv0 = ((const float4*)(c0 + (size_t)lab0 * D))[lane];
            float4 cv1 = ((const float4*)(c1 + (size_t)lab1 * D))[lane];
            float4 cv2 = ((const float4*)(c2 + (size_t)lab2 * D))[lane];
            float4 sv0 = ((const float4*)(se + ((size_t)b * H + 0) * D))[lane];
            float4 sv1 = ((const float4*)(se + ((size_t)b * H + 1) * D))[lane];
            float4 sv2 = ((const float4*)(se + ((size_t)b * H + 2) * D))[lane];

            float prod = 1.0f;
            #pragma unroll
            for (int h = 0; h < H; h++) {
                float4 cv = (h == 0) ? cv0 : (h == 1) ? cv1 : cv2;
                float4 sv = (h == 0) ? sv0 : (h == 1) ? sv1 : sv2;
                float cc = cv.x * cv.x + cv.y * cv.y + cv.z * cv.z + cv.w * cv.w;
                float ee = sv.x * sv.x + sv.y * sv.y + sv.z * sv.z + sv.w * sv.w;
                float dd = cv.x * sv.x + cv.y * sv.y + cv.z * sv.z + cv.w * sv.w;
                #pragma unroll
                for (int o = 16; o > 0; o >>= 1) {
                    cc += __shfl_xor_sync(0xffffffffu, cc, o);
                    ee += __shfl_xor_sync(0xffffffffu, ee, o);
                    dd += __shfl_xor_sync(0xffffffffu, dd, o);
                }
                float s = dd / (fmaxf(sqrtf(cc), 1e-12f) * fmaxf(sqrtf(ee), 1e-12f));
                prod *= (s + 1.0f) * 0.5f;
            }
            if (lane == 0) {
                g_posmul[b] = prod;
                g_lab[b * H + 0] = lab0;
                g_lab[b * H + 1] = lab1;
                g_lab[b * H + 2] = lab2;
            }
        }
        return;
    }

    // ---- sim tile: BT=16 b's x CT=64 c's, 4 outputs per thread ----
    const int h = blockIdx.z;
    const int cbase = blockIdx.x * CT;
    const int b0 = blockIdx.y * BT;
    const float* cents = (h == 0) ? c0 : (h == 1) ? c1 : c2;

    // Load 64 centroid rows (raw), transposed into cn_s[d][c].
    for (int i = tid; i < CT * 32; i += 256) {     // 2048 float4 chunks
        int c = i & (CT - 1), dq = i >> 6;
        int cg = cbase + c;
        float4 v = make_float4(0.f, 0.f, 0.f, 0.f);
        if (cg < CMAX) v = ((const float4*)(cents + (size_t)cg * D))[dq];
        int d = dq * 4;
        cn_s[(d + 0) * CT + c] = v.x;
        cn_s[(d + 1) * CT + c] = v.y;
        cn_s[(d + 2) * CT + c] = v.z;
        cn_s[(d + 3) * CT + c] = v.w;
    }
    // Load 16 se rows (raw) [bi][d].
    for (int i = tid; i < BT * 32; i += 256) {     // 512 float4 chunks
        int bb = i >> 5, dq = i & 31;
        float4 v = ((const float4*)(se + ((size_t)(b0 + bb) * H + h) * D))[dq];
        int d = dq * 4;
        se_s[bb * D + d + 0] = v.x;
        se_s[bb * D + d + 1] = v.y;
        se_s[bb * D + d + 2] = v.z;
        se_s[bb * D + d + 3] = v.w;
    }
    __syncthreads();

    // Centroid norm partials: seg = tid>>6 (0..3) sums 32 d's for c = tid&63.
    {
        int c = tid & (CT - 1), seg = tid >> 6;
        float ss = 0.0f;
        #pragma unroll
        for (int d = seg * 32; d < seg * 32 + 32; d++) {
            float x = cn_s[d * CT + c];
            ss = fmaf(x, x, ss);
        }
        sPart[seg * CT + c] = ss;
    }
    // se norms: warp w handles rows 2w, 2w+1.
    {
        int w = tid >> 5, lane = tid & 31;
        #pragma unroll
        for (int r = 0; r < 2; r++) {
            int row = w * 2 + r;
            float4 v = ((const float4*)(se_s + row * D))[lane];
            float s = v.x * v.x + v.y * v.y + v.z * v.z + v.w * v.w;
            #pragma unroll
            for (int o = 16; o > 0; o >>= 1) s += __shfl_xor_sync(0xffffffffu, s, o);
            if (lane == 0) sInvSe[row] = 1.0f / fmaxf(sqrtf(s), 1e-12f);
        }
    }
    __syncthreads();
    if (tid < CT) {
        float ss = sPart[tid] + sPart[CT + tid] + sPart[2 * CT + tid] + sPart[3 * CT + tid];
        sInvC[tid] = 1.0f / fmaxf(sqrtf(ss), 1e-12f);
    }
    __syncthreads();

    // Main loop: thread (bi = tid>>4, ci = tid&15) computes c = ci*4 .. +3.
    {
        int bi = tid >> 4, ci = tid & 15;
        int cq = ci * 4;
        float a0 = 0.f, a1 = 0.f, a2 = 0.f, a3 = 0.f;
        const float* ses = se_s + bi * D;
        #pragma unroll 8
        for (int d = 0; d < D; d++) {
            float sv = ses[d];
            float4 cv = *((const float4*)(cn_s + d * CT + cq));
            a0 = fmaf(sv, cv.x, a0);
            a1 = fmaf(sv, cv.y, a1);
            a2 = fmaf(sv, cv.z, a2);
            a3 = fmaf(sv, cv.w, a3);
        }
        float invse = sInvSe[bi];
        float4 r;
        r.x = (a0 * sInvC[cq + 0] * invse + 1.0f) * 0.5f;
        r.y = (a1 * sInvC[cq + 1] * invse + 1.0f) * 0.5f;
        r.z = (a2 * sInvC[cq + 2] * invse + 1.0f) * 0.5f;
        r.w = (a3 * sInvC[cq + 3] * invse + 1.0f) * 0.5f;
        *((float4*)(g_S + ((size_t)(b0 + bi) * H + h) * CPAD + cbase + cq)) = r;
    }
}

// ---------------------------------------------------------------------------
// K2: per-b loss, smem-staged. Block = 1024 threads, one block per b.
//     neg row (12 KB) staged via int4 (conflict-free stride-3 reads);
//     S row (3 KB) staged via float4; gathers hit smem, not L1tex replays.
// ---------------------------------------------------------------------------
__global__ void __launch_bounds__(1024)
k_loss(const int* __restrict__ neg, float* __restrict__ out) {
    __shared__ int   sNeg[NNEG * H];     // 12 KB
    __shared__ float sSm[H * CPAD];      // 3 KB
    __shared__ float rL[32];
    __shared__ int   rC[32];
    __shared__ int   sLast;

    const int b = blockIdx.x, tid = threadIdx.x;
    const int w = tid >> 5, lane = tid & 31;

    // Stage neg row: 750 int4 coalesced (b*3000 ints = b*12000 B, 16B-aligned).
    if (tid < 750)
        ((int4*)sNeg)[tid] = ((const int4*)(neg + (size_t)b * NNEG * H))[tid];
    // Stage S row: 192 float4 coalesced.
    if (tid >= 768 && tid < 960)
        ((float4*)sSm)[tid - 768] = ((const float4*)(g_S + (size_t)b * H * CPAD))[tid - 768];
    __syncthreads();

    const int lab0 = g_lab[b * H + 0];
    const int lab1 = g_lab[b * H + 1];
    const int lab2 = g_lab[b * H + 2];

    float sumL = 0.0f;
    bool tn = false;
    if (tid < NNEG) {
        int i0 = sNeg[tid * 3 + 0];      // stride-3: conflict-free (3 coprime 32)
        int i1 = sNeg[tid * 3 + 1];
        int i2 = sNeg[tid * 3 + 2];
        float prod = sSm[i0] * sSm[CPAD + i1] * sSm[2 * CPAD + i2];
        tn = (i0 != lab0) || (i1 != lab1) || (i2 != lab2);
        if (tn) sumL = -__logf(1.0f - prod + EPSF);
    }
    unsigned bm = __ballot_sync(0xffffffffu, tn);
    #pragma unroll
    for (int o = 16; o > 0; o >>= 1)
        sumL += __shfl_xor_sync(0xffffffffu, sumL, o);
    if (lane == 0) { rL[w] = sumL; rC[w] = __popc(bm); }
    __syncthreads();
    if (tid < 32) {
        float sL = rL[tid];
        float sC = (float)rC[tid];
        #pragma unroll
        for (int o = 16; o > 0; o >>= 1) {
            sL += __shfl_xor_sync(0xffffffffu, sL, o);
            sC += __shfl_xor_sync(0xffffffffu, sC, o);
        }
        if (tid == 0) {
            float negl = sL / (sC + EPSF);
            float posl = -__logf(g_posmul[b] + EPSF);
            g_loss[b] = 0.5f * (posl + negl);
            __threadfence();
            unsigned int t = atomicAdd(&g_done, 1u);
            sLast = (t == gridDim.x - 1) ? 1 : 0;
        }
    }
    __syncthreads();

    // Last block: deterministic final mean over B=256 losses.
    if (sLast) {
        __threadfence();
        float v = 0.0f;
        if (tid < B) v = *((volatile float*)&g_loss[tid]);
        if (tid < 256) {
            #pragma unroll
            for (int o = 16; o > 0; o >>= 1) v += __shfl_xor_sync(0xffffffffu, v, o);
            if (lane == 0) rL[w] = v;   // w in 0..7
        }
        __syncthreads();
        if (tid == 0) {
            float total = 0.0f;
            #pragma unroll
            for (int i = 0; i < 8; i++) total += rL[i];
            out[0] = total * (1.0f / (float)B);
            g_done = 0;   // reset for next graph replay
        }
    }
}

// ---------------------------------------------------------------------------
extern "C" void kernel_launch(void* const* d_in, const int* in_sizes, int n_in,
                              void* d_out, int out_size) {
    const float* se  = (const float*)d_in[0];
    const float* c0  = (const float*)d_in[1];
    const float* c1  = (const float*)d_in[2];
    const float* c2  = (const float*)d_in[3];
    const int* i2c0  = (const int*)d_in[4];
    const int* i2c1  = (const int*)d_in[5];
    const int* i2c2  = (const int*)d_in[6];
    const int* index = (const int*)d_in[7];
    const int* neg   = (const int*)d_in[8];
    float* out = (float*)d_out;

    k_sim<<<dim3(4, 16, 4), 256>>>(se, c0, c1, c2, i2c0, i2c1, i2c2, index);
    k_loss<<<B, 1024>>>(neg, out);
}